// round 14
// baseline (speedup 1.0000x reference)
#include <cuda_runtime.h>
#include <cuda_fp16.h>
#include <cstdint>
#include <math.h>

// ---------------- problem constants ----------------
#define NNODES 32768
#define D      384
#define EFEAT  768
#define BATCH  64
#define SEQ    512
#define NGRAPH 512
#define NEDGES 1048576
#define EPS    1e-5f

// ---------------- device scratch (static, no allocs) ----------------
__device__ __half g_x0h[(size_t)NNODES * 320];
__device__ __half g_x0l[(size_t)NNODES * 320];
__device__ __half g_h1[(size_t)NNODES * D];
__device__ __half g_l1[(size_t)NNODES * D];
__device__ __half g_h2[(size_t)NNODES * D];
__device__ __half g_xw[(size_t)NNODES * D];
__device__ int    g_degi[NNODES];
__device__ float  g_isq[NNODES];
__device__ int    g_off[NNODES + 1];
__device__ int    g_cursor[NNODES];
__device__ int    g_csr[NEDGES];
__device__ float  g_sum[7 * EFEAT];
__device__ float  g_sq[7 * EFEAT];
__device__ float  g_hsent[BATCH * EFEAT];
__device__ float  g_outc[BATCH * EFEAT];
__device__ int    g_sel[BATCH * 2];
// folded transposed weights fp16 hi/lo: [N=384][KPAD<=384]
__device__ __half g_wth[5][D * D];
__device__ __half g_wtl[5][D * D];
__device__ float  g_biasf[5][D];

// ================= helpers =================
__device__ __forceinline__ uint32_t smem_u32(const void* p) {
    uint32_t a;
    asm("{ .reg .u64 t; cvta.to.shared.u64 t, %1; cvt.u32.u64 %0, t; }" : "=r"(a) : "l"(p));
    return a;
}
__device__ __forceinline__ void ldsm4(uint32_t* r, uint32_t addr) {
    asm volatile("ldmatrix.sync.aligned.m8n8.x4.shared.b16 {%0,%1,%2,%3}, [%4];"
                 : "=r"(r[0]), "=r"(r[1]), "=r"(r[2]), "=r"(r[3]) : "r"(addr));
}
__device__ __forceinline__ void mma16816f(float* c, const uint32_t* a, uint32_t b0, uint32_t b1) {
    asm volatile("mma.sync.aligned.m16n8k16.row.col.f32.f16.f16.f32 "
                 "{%0,%1,%2,%3},{%4,%5,%6,%7},{%8,%9},{%0,%1,%2,%3};"
                 : "+f"(c[0]), "+f"(c[1]), "+f"(c[2]), "+f"(c[3])
                 : "r"(a[0]), "r"(a[1]), "r"(a[2]), "r"(a[3]), "r"(b0), "r"(b1));
}
#define CP16(d, s) asm volatile("cp.async.cg.shared.global [%0], [%1], 16;" :: "r"(d), "l"(s) : "memory")
#define CP_COMMIT() asm volatile("cp.async.commit_group;" ::: "memory")
#define CP_WAIT0() asm volatile("cp.async.wait_group 0;" ::: "memory")

// K-chunk 64. Row pitch 72 halves = 144 B (36 words ≡ 4 mod 32 → conflict-free ldmatrix).
// stage layout (bytes): Ah@0 (18432) Al@18432 Bh@36864 (9216) Bl@46080 (9216); stride 55296
#define STAGE_STRIDE 55296
#define DYN_SMEM (2 * STAGE_STRIDE + 512)
#define AROW 72

__device__ __forceinline__ float bn_scale_of(const float* sum, const float* sq, int k,
                                             float Mf, const float* gam) {
    float m = sum[k] / Mf;
    float v = sq[k] / Mf - m * m;
    return gam[k] * rsqrtf(v + EPS);
}
__device__ __forceinline__ float bn_shift_of(const float* sum, const float* sq, int k,
                                             float Mf, const float* gam, const float* bet) {
    float m = sum[k] / Mf;
    float v = sq[k] / Mf - m * m;
    float s = gam[k] * rsqrtf(v + EPS);
    return bet[k] - m * s;
}

// ================= misc kernels =================
__global__ void zero_kernel() {
    int i = blockIdx.x * blockDim.x + threadIdx.x;
    if (i < NNODES) g_degi[i] = 0;
    if (i < 7 * EFEAT) { g_sum[i] = 0.f; g_sq[i] = 0.f; }
    if (i < BATCH * EFEAT) g_hsent[i] = 0.f;
}

__global__ void hsent_kernel(const float* __restrict__ lh, const float* __restrict__ fh) {
    int b = blockIdx.x, chunk = blockIdx.y, t = threadIdx.x;
    size_t base = ((size_t)b * SEQ + chunk * 128) * EFEAT + t;
    float s = 0.f;
    for (int ss = 0; ss < 128; ss++)
        s += lh[base + (size_t)ss * EFEAT] + fh[base + (size_t)ss * EFEAT];
    atomicAdd(&g_hsent[b * EFEAT + t], s * (0.5f / 512.0f));
}

// x_nodes fp32 [N,300] -> fp16 hi/lo [N,320] zero-padded
__global__ void xprep_kernel(const float* __restrict__ X) {
    size_t idx = (size_t)blockIdx.x * blockDim.x + threadIdx.x;
    if (idx >= (size_t)NNODES * 320) return;
    int row = (int)(idx / 320), k = (int)(idx % 320);
    float v = (k < 300) ? X[(size_t)row * 300 + k] : 0.f;
    __half h = __float2half_rn(v);
    g_x0h[idx] = h;
    g_x0l[idx] = __float2half_rn(v - __half2float(h));
}

// stage-0 weight prep (no BN fold): W[K,384] -> transposed fp16 hi/lo [384][KPAD]
__global__ void wprep0_kernel(const float* __restrict__ W, int K, int KPAD,
                              __half* __restrict__ oh, __half* __restrict__ ol) {
    int idx = blockIdx.x * blockDim.x + threadIdx.x;
    if (idx >= D * KPAD) return;
    int n = idx / KPAD, k = idx % KPAD;
    float v = (k < K) ? W[(size_t)k * D + n] : 0.f;
    __half h = __float2half_rn(v);
    oh[idx] = h;
    ol[idx] = __float2half_rn(v - __half2float(h));
}

// fused BN-fold: folded weight row (hi/lo) + folded bias, one block per output col n.
__global__ void fold_kernel(const float* __restrict__ W,
                            const float* __restrict__ sum, const float* __restrict__ sq,
                            const float* __restrict__ gam, const float* __restrict__ bet,
                            float Mf, const float* __restrict__ base,
                            __half* __restrict__ oh, __half* __restrict__ ol,
                            float* __restrict__ outb) {
    int n = blockIdx.x, t = threadIdx.x;
    float acc = 0.f;
#pragma unroll
    for (int i = 0; i < 3; i++) {
        int k = t + i * 128;
        float w = W[(size_t)k * D + n];
        float m = sum[k] / Mf;
        float var = sq[k] / Mf - m * m;
        float sc = gam[k] * rsqrtf(var + EPS);
        float sh = bet[k] - m * sc;
        float v = w * sc;
        __half h = __float2half_rn(v);
        oh[(size_t)n * D + k] = h;
        ol[(size_t)n * D + k] = __float2half_rn(v - __half2float(h));
        acc += sh * w;
    }
    __shared__ float red[128];
    red[t] = acc;
    __syncthreads();
    for (int o = 64; o > 0; o >>= 1) {
        if (t < o) red[t] += red[t + o];
        __syncthreads();
    }
    if (t == 0) outb[n] = (base ? base[n] : 0.f) + red[0];
}

// fp32 column stats
__global__ void stats_kernel(const float* __restrict__ X, int M, int N,
                             float* __restrict__ sum, float* __restrict__ sq) {
    int col = threadIdx.x;
    int rows_per = (M + gridDim.x - 1) / gridDim.x;
    int r0 = blockIdx.x * rows_per;
    int r1 = min(M, r0 + rows_per);
    float s = 0.f, q = 0.f;
    for (int r = r0; r < r1; r++) {
        float v = X[(size_t)r * N + col];
        s += v; q += v * v;
    }
    atomicAdd(&sum[col], s);
    atomicAdd(&sq[col], q);
}

// single fp16 column stats
__global__ void stats_f16_kernel(const __half* __restrict__ H,
                                 float* __restrict__ sum, float* __restrict__ sq) {
    int col = threadIdx.x;
    int rows_per = (NNODES + gridDim.x - 1) / gridDim.x;
    int r0 = blockIdx.x * rows_per;
    int r1 = min(NNODES, r0 + rows_per);
    float s = 0.f, q = 0.f;
    for (int r = r0; r < r1; r++) {
        float v = __half2float(H[(size_t)r * D + col]);
        s += v; q += v * v;
    }
    atomicAdd(&sum[col], s);
    atomicAdd(&sq[col], q);
}

// ================= cp.async tile stage (K-chunk 64) =================
template <int TP>
__device__ __forceinline__ void issue_tiles(uint32_t sbase, int stage, int tid,
                                            const __half* Ah, const __half* Al,
                                            const __half* Bh, const __half* Bl,
                                            int bm, int bn, int KPAD, int chunk) {
    uint32_t sb = sbase + stage * STAGE_STRIDE;
#pragma unroll
    for (int it = 0; it < 4; it++) {
        int i = tid + it * 256;            // 0..1023 : 128 rows x 8 16B-units
        int row = i >> 3, c16 = i & 7;
        uint32_t d = sb + row * 144 + c16 * 16;
        const __half* sa = Ah + (size_t)(bm + row) * KPAD + chunk * 64 + c16 * 8;
        CP16(d, sa);
        if (TP) {
            const __half* sl = Al + (size_t)(bm + row) * KPAD + chunk * 64 + c16 * 8;
            CP16(d + 18432, sl);
        }
    }
#pragma unroll
    for (int it = 0; it < 2; it++) {
        int i = tid + it * 256;            // 0..511 : 64 rows x 8 16B-units
        int row = i >> 3, c16 = i & 7;
        uint32_t d = sb + 36864 + row * 144 + c16 * 16;
        const __half* sbh = Bh + (size_t)(bn + row) * KPAD + chunk * 64 + c16 * 8;
        const __half* sbl = Bl + (size_t)(bn + row) * KPAD + chunk * 64 + c16 * 8;
        CP16(d, sbh);
        CP16(d + 9216, sbl);
    }
}

// ================= mma.sync fp16 GEMM, double-buffered, K-chunk 64, 1 sync/chunk =========
// TP=1: C = (Ah+Al)@(Bh+Bl)^T dropping AlBl (err ~2^-22)
// TP=0: C = Ah@(Bh+Bl)^T (err ~2^-11; A-lo never loaded)
// block 128x64, 8 warps (4m x 2n); fused column stats optional.
// Output: Cl!=null -> hi/lo fp16 pair; Cl==null -> single fp16 in Ch.
template <int NCH, int TP>
__global__ void __launch_bounds__(256, 2)
mma_gemm(const __half* __restrict__ Ah, const __half* __restrict__ Al,
         const __half* __restrict__ Bh, const __half* __restrict__ Bl,
         const float* __restrict__ biasf,
         __half* __restrict__ Ch, __half* __restrict__ Cl,
         int KPAD, int do_relu,
         float* __restrict__ gsum, float* __restrict__ gsq) {
    extern __shared__ char dsm[];
    float* scs = (float*)(dsm + 2 * STAGE_STRIDE);
    float* scq = scs + 64;
    uint32_t sbase = smem_u32(dsm);

    int tid = threadIdx.x;
    int wid = tid >> 5, lane = tid & 31;
    int bm = blockIdx.y * 128, bn = blockIdx.x * 64;
    int wm = wid & 3, wn = wid >> 2;

    if (tid < 64) { scs[tid] = 0.f; scq[tid] = 0.f; }

    float acc[2][4][4];
#pragma unroll
    for (int i = 0; i < 2; i++)
#pragma unroll
        for (int j = 0; j < 4; j++)
#pragma unroll
            for (int k = 0; k < 4; k++) acc[i][j][k] = 0.f;

    int g = lane >> 3, r = lane & 7;
    int frag_row = (g & 1) * 8 + r;
    int frag_col = (g >> 1) * 8;

    issue_tiles<TP>(sbase, 0, tid, Ah, Al, Bh, Bl, bm, bn, KPAD, 0);
    CP_COMMIT();

#pragma unroll
    for (int c = 0; c < NCH; c++) {
        // wait for stage c, publish it; the same barrier fences compute(c-1)
        // readers before issue(c+1) -- and (transitively) issue(c+2) overwriting
        // buffer (c&1) can only happen after next iteration's barrier.
        CP_WAIT0();
        __syncthreads();
        if (c + 1 < NCH) {
            issue_tiles<TP>(sbase, (c + 1) & 1, tid, Ah, Al, Bh, Bl, bm, bn, KPAD, c + 1);
            CP_COMMIT();
        }

        uint32_t baseAh = sbase + (c & 1) * STAGE_STRIDE;
        uint32_t baseAl = baseAh + 18432;
        uint32_t baseBh = baseAh + 36864;
        uint32_t baseBl = baseAh + 46080;
#pragma unroll
        for (int ks = 0; ks < 4; ks++) {
            int k0 = ks * 16;
            uint32_t ah[2][4], al[2][4], bh[2][4], bl[2][4];
#pragma unroll
            for (int mi = 0; mi < 2; mi++) {
                int row = wm * 32 + mi * 16 + frag_row;
                uint32_t off = (uint32_t)(row * AROW + k0 + frag_col) * 2;
                ldsm4(ah[mi], baseAh + off);
                if (TP) ldsm4(al[mi], baseAl + off);
            }
#pragma unroll
            for (int j = 0; j < 2; j++) {
                int row = wn * 32 + j * 16 + frag_row;
                uint32_t off = (uint32_t)(row * AROW + k0 + frag_col) * 2;
                ldsm4(bh[j], baseBh + off);
                ldsm4(bl[j], baseBl + off);
            }
#pragma unroll
            for (int mi = 0; mi < 2; mi++)
#pragma unroll
                for (int nt = 0; nt < 4; nt++) {
                    int j = nt >> 1, sel = nt & 1;
                    mma16816f(acc[mi][nt], ah[mi], bh[j][sel], bh[j][sel + 2]);
                    mma16816f(acc[mi][nt], ah[mi], bl[j][sel], bl[j][sel + 2]);
                    if (TP)
                        mma16816f(acc[mi][nt], al[mi], bh[j][sel], bh[j][sel + 2]);
                }
        }
    }

    // ---- epilogue ----
    int tm = lane >> 2;
    int tn = (lane & 3) * 2;
    bool dosum = (gsum != nullptr);
#pragma unroll
    for (int nt = 0; nt < 4; nt++) {
        float s0 = 0.f, s1 = 0.f, q0 = 0.f, q1 = 0.f;
        int col = bn + wn * 32 + nt * 8 + tn;
        float b0 = biasf[col], b1 = biasf[col + 1];
#pragma unroll
        for (int mi = 0; mi < 2; mi++) {
            int row0 = bm + wm * 32 + mi * 16 + tm;
            float v0 = acc[mi][nt][0] + b0, v1 = acc[mi][nt][1] + b1;
            float v2 = acc[mi][nt][2] + b0, v3 = acc[mi][nt][3] + b1;
            if (do_relu) {
                v0 = fmaxf(v0, 0.f); v1 = fmaxf(v1, 0.f);
                v2 = fmaxf(v2, 0.f); v3 = fmaxf(v3, 0.f);
            }
            __half h0 = __float2half_rn(v0), h1 = __float2half_rn(v1);
            __half h2 = __float2half_rn(v2), h3 = __float2half_rn(v3);
            uint32_t ph01 = ((uint32_t)__half_as_ushort(h1) << 16) | __half_as_ushort(h0);
            uint32_t ph23 = ((uint32_t)__half_as_ushort(h3) << 16) | __half_as_ushort(h2);
            *(uint32_t*)&Ch[(size_t)row0 * D + col] = ph01;
            *(uint32_t*)&Ch[(size_t)(row0 + 8) * D + col] = ph23;
            if (Cl) {
                __half l0 = __float2half_rn(v0 - __half2float(h0));
                __half l1 = __float2half_rn(v1 - __half2float(h1));
                __half l2 = __float2half_rn(v2 - __half2float(h2));
                __half l3 = __float2half_rn(v3 - __half2float(h3));
                uint32_t pl01 = ((uint32_t)__half_as_ushort(l1) << 16) | __half_as_ushort(l0);
                uint32_t pl23 = ((uint32_t)__half_as_ushort(l3) << 16) | __half_as_ushort(l2);
                *(uint32_t*)&Cl[(size_t)row0 * D + col] = pl01;
                *(uint32_t*)&Cl[(size_t)(row0 + 8) * D + col] = pl23;
            }
            s0 += v0 + v2; s1 += v1 + v3;
            q0 += v0 * v0 + v2 * v2; q1 += v1 * v1 + v3 * v3;
        }
        if (dosum) {
#pragma unroll
            for (int o = 4; o < 32; o <<= 1) {
                s0 += __shfl_xor_sync(0xffffffffu, s0, o);
                s1 += __shfl_xor_sync(0xffffffffu, s1, o);
                q0 += __shfl_xor_sync(0xffffffffu, q0, o);
                q1 += __shfl_xor_sync(0xffffffffu, q1, o);
            }
            if (lane < 4) {
                int cl = wn * 32 + nt * 8 + lane * 2;
                atomicAdd(&scs[cl], s0); atomicAdd(&scs[cl + 1], s1);
                atomicAdd(&scq[cl], q0); atomicAdd(&scq[cl + 1], q1);
            }
        }
    }
    if (dosum) {
        __syncthreads();
        if (tid < 64) {
            atomicAdd(&gsum[bn + tid], scs[tid]);
            atomicAdd(&gsq[bn + tid], scq[tid]);
        }
    }
}

// ================= graph kernels =================
__global__ void deg_kernel(const int* __restrict__ dst) {
    int e = blockIdx.x * blockDim.x + threadIdx.x;
    if (e < NEDGES) atomicAdd(&g_degi[dst[e]], 1);
}
__global__ void isq_kernel() {
    int n = blockIdx.x * blockDim.x + threadIdx.x;
    if (n < NNODES) g_isq[n] = rsqrtf((float)g_degi[n] + 1.0f);
}
__global__ void scan_kernel() {
    __shared__ int sh[1024];
    int tid = threadIdx.x;
    int base = tid * 32;
    int local[32];
    int s = 0;
    for (int i = 0; i < 32; i++) { local[i] = s; s += g_degi[base + i]; }
    sh[tid] = s;
    __syncthreads();
    for (int off = 1; off < 1024; off <<= 1) {
        int v = 0;
        if (tid >= off) v = sh[tid - off];
        __syncthreads();
        if (tid >= off) sh[tid] += v;
        __syncthreads();
    }
    int prev = (tid == 0) ? 0 : sh[tid - 1];
    for (int i = 0; i < 32; i++) {
        g_off[base + i] = prev + local[i];
        g_cursor[base + i] = prev + local[i];
    }
    if (tid == 1023) g_off[NNODES] = sh[1023];
}
__global__ void scatter_kernel(const int* __restrict__ src, const int* __restrict__ dst) {
    int e = blockIdx.x * blockDim.x + threadIdx.x;
    if (e < NEDGES) {
        int d = dst[e];
        int p = atomicAdd(&g_cursor[d], 1);
        g_csr[p] = src[e];
    }
}

// GCN aggregation: fp16 in (u32/half2 loads), fp32 accumulate, bias+relu, single fp16 out
// inner loop unrolled x4 for memory-level parallelism
#define AGG_T 192
__global__ void __launch_bounds__(AGG_T)
agg_kernel(const __half* __restrict__ xw, const float* __restrict__ bias,
           __half* __restrict__ oh) {
    int n = blockIdx.x;
    int t = threadIdx.x;
    float isqn = g_isq[n];
    float sc = isqn * isqn;
    const uint32_t* selfrow = (const uint32_t*)(xw + (size_t)n * D);
    uint32_t su = selfrow[t];
    __half2 sh2 = *(__half2*)&su;
    float a0 = __low2float(sh2) * sc;
    float a1 = __high2float(sh2) * sc;

    int beg = g_off[n], end = g_off[n + 1];
    __shared__ int ssrc[AGG_T];
    __shared__ float scoef[AGG_T];
    for (int p = beg; p < end; p += AGG_T) {
        int cnt = min(AGG_T, end - p);
        __syncthreads();
        if (t < cnt) {
            int s = g_csr[p + t];
            ssrc[t] = s;
            scoef[t] = g_isq[s] * isqn;
        }
        __syncthreads();
        int j = 0;
        for (; j + 4 <= cnt; j += 4) {
            int s0i = ssrc[j], s1i = ssrc[j + 1], s2i = ssrc[j + 2], s3i = ssrc[j + 3];
            float c0 = scoef[j], c1 = scoef[j + 1], c2 = scoef[j + 2], c3 = scoef[j + 3];
            uint32_t u0 = ((const uint32_t*)(xw + (size_t)s0i * D))[t];
            uint32_t u1 = ((const uint32_t*)(xw + (size_t)s1i * D))[t];
            uint32_t u2 = ((const uint32_t*)(xw + (size_t)s2i * D))[t];
            uint32_t u3 = ((const uint32_t*)(xw + (size_t)s3i * D))[t];
            __half2 v0 = *(__half2*)&u0, v1 = *(__half2*)&u1;
            __half2 v2 = *(__half2*)&u2, v3 = *(__half2*)&u3;
            a0 += __low2float(v0) * c0 + __low2float(v1) * c1
                + __low2float(v2) * c2 + __low2float(v3) * c3;
            a1 += __high2float(v0) * c0 + __high2float(v1) * c1
                + __high2float(v2) * c2 + __high2float(v3) * c3;
        }
        for (; j < cnt; j++) {
            int s = ssrc[j];
            float c = scoef[j];
            uint32_t u = ((const uint32_t*)(xw + (size_t)s * D))[t];
            __half2 h2v = *(__half2*)&u;
            a0 += __low2float(h2v) * c;
            a1 += __high2float(h2v) * c;
        }
    }
    float2 bb = *(const float2*)(bias + 2 * t);
    float v0 = fmaxf(a0 + bb.x, 0.f);
    float v1 = fmaxf(a1 + bb.y, 0.f);
    __half h0 = __float2half_rn(v0);
    __half h1 = __float2half_rn(v1);
    uint32_t ph = ((uint32_t)__half_as_ushort(h1) << 16) | __half_as_ushort(h0);
    ((uint32_t*)(oh + (size_t)n * D))[t] = ph;
}

// ================= tail kernels =================
__global__ void sel_kernel(const int* __restrict__ mask) {
    int b = threadIdx.x;
    int c = 0;
    for (int i = 0; i < NGRAPH; i++) {
        if (mask[b * NGRAPH + i]) {
            if (c < 2) g_sel[b * 2 + c] = i;
            c++;
        }
    }
}
// fused: gather 2 masked nodes (BN slot-4 affine inline) -> relu(flat @ w_cat + b_cat)
// + fused column stats (slot 5). One block per sample, 768 threads.
__global__ void cat_gemm_kernel(const __half* __restrict__ H,
                                const float* __restrict__ sum4, const float* __restrict__ sq4,
                                const float* __restrict__ gam, const float* __restrict__ bet,
                                const float* __restrict__ Wc, const float* __restrict__ bc,
                                float* __restrict__ sum, float* __restrict__ sq) {
    __shared__ float sh[EFEAT];
    int b = blockIdx.x, t = threadIdx.x;
    {
        int j = t / D, tloc = t % D;
        int node = b * NGRAPH + g_sel[b * 2 + j];
        float v = __half2float(H[(size_t)node * D + tloc]);
        float s = bn_scale_of(sum4, sq4, tloc, (float)NNODES, gam);
        float shf = bn_shift_of(sum4, sq4, tloc, (float)NNODES, gam, bet);
        sh[t] = v * s + shf;
    }
    __syncthreads();
    float s = bc[t];
    for (int k = 0; k < EFEAT; k++) s += sh[k] * Wc[(size_t)k * EFEAT + t];
    s = fmaxf(s, 0.f);
    g_outc[b * EFEAT + t] = s;
    atomicAdd(&sum[t], s);
    atomicAdd(&sq[t], s * s);
}
__global__ void attout_kernel(const float* __restrict__ sum5, const float* __restrict__ sq5,
                              const float* __restrict__ sum6, const float* __restrict__ sq6,
                              const float* __restrict__ bg, const float* __restrict__ bb,
                              const float* __restrict__ wout, const float* __restrict__ bout,
                              float* __restrict__ out) {
    __shared__ float satt[EFEAT];
    int b = blockIdx.x, t = threadIdx.x;
    float Bf = (float)BATCH;
    float m0 = sum5[t] / Bf, v0 = sq5[t] / Bf - m0 * m0;
    float oc = bg[t] * (g_outc[b * EFEAT + t] - m0) * rsqrtf(v0 + EPS) + bb[t];
    float m1 = sum6[t] / Bf, v1 = sq6[t] / Bf - m1 * m1;
    float hh = bg[EFEAT + t] * (g_hsent[b * EFEAT + t] - m1) * rsqrtf(v1 + EPS) + bb[EFEAT + t];
    satt[t] = hh + oc;
    __syncthreads();
    int w = t >> 5, lane = t & 31;
    if (w < 3) {
        int c = w;
        float p = 0.f;
        for (int e = lane; e < EFEAT; e += 32) p += satt[e] * wout[e * 3 + c];
#pragma unroll
        for (int o = 16; o > 0; o >>= 1) p += __shfl_xor_sync(0xffffffffu, p, o);
        if (lane == 0) out[b * 3 + c] = p + bout[c];
    }
}

// ============================== launch ==============================
extern "C" void kernel_launch(void* const* d_in, const int* in_sizes, int n_in,
                              void* d_out, int out_size) {
    const float* last_h  = (const float*)d_in[0];
    const float* first_h = (const float*)d_in[1];
    const float* x_nodes = (const float*)d_in[2];
    const int*   eidx    = (const int*)d_in[3];
    const int*   mask    = (const int*)d_in[4];
    const float* w_pre1  = (const float*)d_in[5];
    const float* b_pre1  = (const float*)d_in[6];
    const float* w_pre2  = (const float*)d_in[7];
    const float* b_pre2  = (const float*)d_in[8];
    const float* w_conv  = (const float*)d_in[9];
    const float* b_conv  = (const float*)d_in[10];
    const float* bng_g   = (const float*)d_in[11];
    const float* bng_b   = (const float*)d_in[12];
    const float* w_post1 = (const float*)d_in[13];
    const float* b_post1 = (const float*)d_in[14];
    const float* w_post2 = (const float*)d_in[15];
    const float* b_post2 = (const float*)d_in[16];
    const float* w_cat   = (const float*)d_in[17];
    const float* b_cat   = (const float*)d_in[18];
    const float* bn_g    = (const float*)d_in[19];
    const float* bn_b    = (const float*)d_in[20];
    const float* w_out   = (const float*)d_in[21];
    const float* b_out   = (const float*)d_in[22];
    float* out = (float*)d_out;

    const int* esrc = eidx;
    const int* edst = eidx + NEDGES;

    float *sum, *sq, *hs, *bfp;
    __half *x0h, *x0l, *h1, *l1, *h2, *wth, *wtl, *xw;
    cudaGetSymbolAddress((void**)&sum, g_sum);
    cudaGetSymbolAddress((void**)&sq, g_sq);
    cudaGetSymbolAddress((void**)&hs, g_hsent);
    cudaGetSymbolAddress((void**)&bfp, g_biasf);
    cudaGetSymbolAddress((void**)&xw, g_xw);
    cudaGetSymbolAddress((void**)&x0h, g_x0h);
    cudaGetSymbolAddress((void**)&x0l, g_x0l);
    cudaGetSymbolAddress((void**)&h1, g_h1);
    cudaGetSymbolAddress((void**)&l1, g_l1);
    cudaGetSymbolAddress((void**)&h2, g_h2);
    cudaGetSymbolAddress((void**)&wth, g_wth);
    cudaGetSymbolAddress((void**)&wtl, g_wtl);

    cudaFuncSetAttribute(mma_gemm<5, 1>, cudaFuncAttributeMaxDynamicSharedMemorySize, DYN_SMEM);
    cudaFuncSetAttribute(mma_gemm<6, 1>, cudaFuncAttributeMaxDynamicSharedMemorySize, DYN_SMEM);
    cudaFuncSetAttribute(mma_gemm<6, 0>, cudaFuncAttributeMaxDynamicSharedMemorySize, DYN_SMEM);

    const float Mf = (float)NNODES;
    dim3 gg(D / 64, NNODES / 128);   // (6, 256) — 128x64 tiles, 2 CTA/SM

    cudaStream_t s1, s2;
    cudaEvent_t e0, e1, e2, e3;
    cudaStreamCreateWithFlags(&s1, cudaStreamNonBlocking);
    cudaStreamCreateWithFlags(&s2, cudaStreamNonBlocking);
    cudaEventCreateWithFlags(&e0, cudaEventDisableTiming);
    cudaEventCreateWithFlags(&e1, cudaEventDisableTiming);
    cudaEventCreateWithFlags(&e2, cudaEventDisableTiming);
    cudaEventCreateWithFlags(&e3, cudaEventDisableTiming);

    zero_kernel<<<192, 256>>>();
    cudaEventRecord(e0, 0);
    cudaStreamWaitEvent(s1, e0, 0);
    cudaStreamWaitEvent(s2, e0, 0);

    // side stream 1: sentence branch + its stats (slot 6)
    hsent_kernel<<<dim3(BATCH, 4), EFEAT, 0, s1>>>(last_h, first_h);
    stats_kernel<<<1, EFEAT, 0, s1>>>(hs, BATCH, EFEAT, sum + 6 * EFEAT, sq + 6 * EFEAT);
    cudaEventRecord(e1, s1);

    // side stream 2: stage-0 weight prep (joins before GEMM1), then CSR chain
    wprep0_kernel<<<(D * 320 + 255) / 256, 256, 0, s2>>>(w_pre1, 300, 320,
                                                         wth + 0 * D * D, wtl + 0 * D * D);
    cudaEventRecord(e3, s2);
    deg_kernel<<<NEDGES / 256, 256, 0, s2>>>(edst);
    isq_kernel<<<NNODES / 256, 256, 0, s2>>>();
    scan_kernel<<<1, 1024, 0, s2>>>();
    scatter_kernel<<<NEDGES / 256, 256, 0, s2>>>(esrc, edst);
    sel_kernel<<<1, BATCH, 0, s2>>>(mask);
    cudaEventRecord(e2, s2);

    // main: input prep
    xprep_kernel<<<(NNODES * 320 + 255) / 256, 256>>>(x_nodes);
    cudaStreamWaitEvent(0, e3, 0);

    // GEMM1 (3-pass, K=320: 5 chunks) -> h1/l1, fused stats slot 0 (bng row 0)
    mma_gemm<5, 1><<<gg, 256, DYN_SMEM>>>(x0h, x0l, wth + 0 * D * D, wtl + 0 * D * D, b_pre1,
                                          h1, l1, 320, 1, sum + 0 * EFEAT, sq + 0 * EFEAT);
    fold_kernel<<<D, 128>>>(w_pre2, sum + 0 * EFEAT, sq + 0 * EFEAT,
                            bng_g + 0 * D, bng_b + 0 * D, Mf, b_pre2,
                            wth + 1 * D * D, wtl + 1 * D * D, bfp + 1 * D);

    // GEMM2 (3-pass, single fp16 out — G3 consumes hi only) -> h2, stats slot 1 (bng row 1)
    mma_gemm<6, 1><<<gg, 256, DYN_SMEM>>>(h1, l1, wth + 1 * D * D, wtl + 1 * D * D, bfp + 1 * D,
                                          h2, nullptr, D, 1, sum + 1 * EFEAT, sq + 1 * EFEAT);
    fold_kernel<<<D, 128>>>(w_conv + 2 * D * D, sum + 1 * EFEAT, sq + 1 * EFEAT,
                            bng_g + 1 * D, bng_b + 1 * D, Mf, nullptr,
                            wth + 2 * D * D, wtl + 2 * D * D, bfp + 2 * D);

    // GEMM3 (2-pass; output fp16-rounded anyway) -> single fp16 xw
    mma_gemm<6, 0><<<gg, 256, DYN_SMEM>>>(h2, nullptr, wth + 2 * D * D, wtl + 2 * D * D, bfp + 2 * D,
                                          xw, nullptr, D, 0, nullptr, nullptr);

    // join CSR stream, aggregate (single fp16 out), stats slot 2 (bng row 4)
    cudaStreamWaitEvent(0, e2, 0);
    agg_kernel<<<NNODES, AGG_T>>>(xw, b_conv + 2 * D, h1);
    stats_f16_kernel<<<256, D>>>(h1, sum + 2 * EFEAT, sq + 2 * EFEAT);
    fold_kernel<<<D, 128>>>(w_post1, sum + 2 * EFEAT, sq + 2 * EFEAT,
                            bng_g + 4 * D, bng_b + 4 * D, Mf, b_post1,
                            wth + 3 * D * D, wtl + 3 * D * D, bfp + 3 * D);

    // GEMM4 (2-pass, single fp16 out) -> h2, stats slot 3 (bng row 5)
    mma_gemm<6, 0><<<gg, 256, DYN_SMEM>>>(h1, nullptr, wth + 3 * D * D, wtl + 3 * D * D, bfp + 3 * D,
                                          h2, nullptr, D, 1, sum + 3 * EFEAT, sq + 3 * EFEAT);
    fold_kernel<<<D, 128>>>(w_post2, sum + 3 * EFEAT, sq + 3 * EFEAT,
                            bng_g + 5 * D, bng_b + 5 * D, Mf, b_post2,
                            wth + 4 * D * D, wtl + 4 * D * D, bfp + 4 * D);

    // GEMM5 (2-pass, single fp16 out; only 128 rows + stats consumed) -> h1, stats slot 4
    mma_gemm<6, 0><<<gg, 256, DYN_SMEM>>>(h2, nullptr, wth + 4 * D * D, wtl + 4 * D * D, bfp + 4 * D,
                                          h1, nullptr, D, 1, sum + 4 * EFEAT, sq + 4 * EFEAT);

    // tail: fused gather+cat-MLP (+stats slot 5) -> att+out
    cat_gemm_kernel<<<BATCH, EFEAT>>>(h1, sum + 4 * EFEAT, sq + 4 * EFEAT,
                                      bng_g + 6 * D, bng_b + 6 * D,
                                      w_cat, b_cat, sum + 5 * EFEAT, sq + 5 * EFEAT);
    cudaStreamWaitEvent(0, e1, 0);
    attout_kernel<<<BATCH, EFEAT>>>(sum + 5 * EFEAT, sq + 5 * EFEAT,
                                    sum + 6 * EFEAT, sq + 6 * EFEAT,
                                    bn_g, bn_b, w_out, b_out, out);

    cudaEventDestroy(e0);
    cudaEventDestroy(e1);
    cudaEventDestroy(e2);
    cudaEventDestroy(e3);
    cudaStreamDestroy(s1);
    cudaStreamDestroy(s2);
}

// round 15
// speedup vs baseline: 1.0050x; 1.0050x over previous
#include <cuda_runtime.h>
#include <cuda_fp16.h>
#include <cstdint>
#include <math.h>

// ---------------- problem constants ----------------
#define NNODES 32768
#define D      384
#define EFEAT  768
#define BATCH  64
#define SEQ    512
#define NGRAPH 512
#define NEDGES 1048576
#define EPS    1e-5f

// ---------------- device scratch (static, no allocs) ----------------
__device__ __half g_x0h[(size_t)NNODES * 320];
__device__ __half g_x0l[(size_t)NNODES * 320];
__device__ __half g_h1[(size_t)NNODES * D];
__device__ __half g_l1[(size_t)NNODES * D];
__device__ __half g_h2[(size_t)NNODES * D];
__device__ __half g_xw[(size_t)NNODES * D];
__device__ int    g_degi[NNODES];
__device__ float  g_isq[NNODES];
__device__ int    g_off[NNODES + 1];
__device__ int    g_cursor[NNODES];
__device__ int    g_csr[NEDGES];
__device__ float  g_sum[7 * EFEAT];
__device__ float  g_sq[7 * EFEAT];
__device__ float  g_hsent[BATCH * EFEAT];
__device__ float  g_outc[BATCH * EFEAT];
__device__ int    g_sel[BATCH * 2];
// folded transposed weights fp16 hi/lo: [N=384][KPAD<=384]
__device__ __half g_wth[5][D * D];
__device__ __half g_wtl[5][D * D];
__device__ float  g_biasf[5][D];

// ================= helpers =================
__device__ __forceinline__ uint32_t smem_u32(const void* p) {
    uint32_t a;
    asm("{ .reg .u64 t; cvta.to.shared.u64 t, %1; cvt.u32.u64 %0, t; }" : "=r"(a) : "l"(p));
    return a;
}
__device__ __forceinline__ void ldsm4(uint32_t* r, uint32_t addr) {
    asm volatile("ldmatrix.sync.aligned.m8n8.x4.shared.b16 {%0,%1,%2,%3}, [%4];"
                 : "=r"(r[0]), "=r"(r[1]), "=r"(r[2]), "=r"(r[3]) : "r"(addr));
}
__device__ __forceinline__ void mma16816f(float* c, const uint32_t* a, uint32_t b0, uint32_t b1) {
    asm volatile("mma.sync.aligned.m16n8k16.row.col.f32.f16.f16.f32 "
                 "{%0,%1,%2,%3},{%4,%5,%6,%7},{%8,%9},{%0,%1,%2,%3};"
                 : "+f"(c[0]), "+f"(c[1]), "+f"(c[2]), "+f"(c[3])
                 : "r"(a[0]), "r"(a[1]), "r"(a[2]), "r"(a[3]), "r"(b0), "r"(b1));
}
#define CP16(d, s) asm volatile("cp.async.cg.shared.global [%0], [%1], 16;" :: "r"(d), "l"(s) : "memory")
#define CP_COMMIT() asm volatile("cp.async.commit_group;" ::: "memory")
#define CP_WAIT0() asm volatile("cp.async.wait_group 0;" ::: "memory")

// K-chunk 64. Row pitch 72 halves = 144 B (36 words ≡ 4 mod 32 → conflict-free ldmatrix).
// stage layout (bytes): Ah@0 (18432) Al@18432 Bh@36864 (9216) Bl@46080 (9216); stride 55296
#define STAGE_STRIDE 55296
#define DYN_SMEM (2 * STAGE_STRIDE + 512)
#define AROW 72

__device__ __forceinline__ float bn_scale_of(const float* sum, const float* sq, int k,
                                             float Mf, const float* gam) {
    float m = sum[k] / Mf;
    float v = sq[k] / Mf - m * m;
    return gam[k] * rsqrtf(v + EPS);
}
__device__ __forceinline__ float bn_shift_of(const float* sum, const float* sq, int k,
                                             float Mf, const float* gam, const float* bet) {
    float m = sum[k] / Mf;
    float v = sq[k] / Mf - m * m;
    float s = gam[k] * rsqrtf(v + EPS);
    return bet[k] - m * s;
}

// ================= misc kernels =================
__global__ void zero_kernel() {
    int i = blockIdx.x * blockDim.x + threadIdx.x;
    if (i < NNODES) g_degi[i] = 0;
    if (i < 7 * EFEAT) { g_sum[i] = 0.f; g_sq[i] = 0.f; }
    if (i < BATCH * EFEAT) g_hsent[i] = 0.f;
}

__global__ void hsent_kernel(const float* __restrict__ lh, const float* __restrict__ fh) {
    int b = blockIdx.x, chunk = blockIdx.y, t = threadIdx.x;
    size_t base = ((size_t)b * SEQ + chunk * 128) * EFEAT + t;
    float s = 0.f;
    for (int ss = 0; ss < 128; ss++)
        s += lh[base + (size_t)ss * EFEAT] + fh[base + (size_t)ss * EFEAT];
    atomicAdd(&g_hsent[b * EFEAT + t], s * (0.5f / 512.0f));
}

// x_nodes fp32 [N,300] -> fp16 hi/lo [N,320] zero-padded
__global__ void xprep_kernel(const float* __restrict__ X) {
    size_t idx = (size_t)blockIdx.x * blockDim.x + threadIdx.x;
    if (idx >= (size_t)NNODES * 320) return;
    int row = (int)(idx / 320), k = (int)(idx % 320);
    float v = (k < 300) ? X[(size_t)row * 300 + k] : 0.f;
    __half h = __float2half_rn(v);
    g_x0h[idx] = h;
    g_x0l[idx] = __float2half_rn(v - __half2float(h));
}

// stage-0 weight prep (no BN fold): W[K,384] -> transposed fp16 hi/lo [384][KPAD]
__global__ void wprep0_kernel(const float* __restrict__ W, int K, int KPAD,
                              __half* __restrict__ oh, __half* __restrict__ ol) {
    int idx = blockIdx.x * blockDim.x + threadIdx.x;
    if (idx >= D * KPAD) return;
    int n = idx / KPAD, k = idx % KPAD;
    float v = (k < K) ? W[(size_t)k * D + n] : 0.f;
    __half h = __float2half_rn(v);
    oh[idx] = h;
    ol[idx] = __float2half_rn(v - __half2float(h));
}

// fused BN-fold: folded weight row (hi/lo) + folded bias, one block per output col n.
__global__ void fold_kernel(const float* __restrict__ W,
                            const float* __restrict__ sum, const float* __restrict__ sq,
                            const float* __restrict__ gam, const float* __restrict__ bet,
                            float Mf, const float* __restrict__ base,
                            __half* __restrict__ oh, __half* __restrict__ ol,
                            float* __restrict__ outb) {
    int n = blockIdx.x, t = threadIdx.x;
    float acc = 0.f;
#pragma unroll
    for (int i = 0; i < 3; i++) {
        int k = t + i * 128;
        float w = W[(size_t)k * D + n];
        float m = sum[k] / Mf;
        float var = sq[k] / Mf - m * m;
        float sc = gam[k] * rsqrtf(var + EPS);
        float sh = bet[k] - m * sc;
        float v = w * sc;
        __half h = __float2half_rn(v);
        oh[(size_t)n * D + k] = h;
        ol[(size_t)n * D + k] = __float2half_rn(v - __half2float(h));
        acc += sh * w;
    }
    __shared__ float red[128];
    red[t] = acc;
    __syncthreads();
    for (int o = 64; o > 0; o >>= 1) {
        if (t < o) red[t] += red[t + o];
        __syncthreads();
    }
    if (t == 0) outb[n] = (base ? base[n] : 0.f) + red[0];
}

// fp32 column stats
__global__ void stats_kernel(const float* __restrict__ X, int M, int N,
                             float* __restrict__ sum, float* __restrict__ sq) {
    int col = threadIdx.x;
    int rows_per = (M + gridDim.x - 1) / gridDim.x;
    int r0 = blockIdx.x * rows_per;
    int r1 = min(M, r0 + rows_per);
    float s = 0.f, q = 0.f;
    for (int r = r0; r < r1; r++) {
        float v = X[(size_t)r * N + col];
        s += v; q += v * v;
    }
    atomicAdd(&sum[col], s);
    atomicAdd(&sq[col], q);
}

// single fp16 column stats
__global__ void stats_f16_kernel(const __half* __restrict__ H,
                                 float* __restrict__ sum, float* __restrict__ sq) {
    int col = threadIdx.x;
    int rows_per = (NNODES + gridDim.x - 1) / gridDim.x;
    int r0 = blockIdx.x * rows_per;
    int r1 = min(NNODES, r0 + rows_per);
    float s = 0.f, q = 0.f;
    for (int r = r0; r < r1; r++) {
        float v = __half2float(H[(size_t)r * D + col]);
        s += v; q += v * v;
    }
    atomicAdd(&sum[col], s);
    atomicAdd(&sq[col], q);
}

// ================= cp.async tile stage (K-chunk 64) =================
template <int TP>
__device__ __forceinline__ void issue_tiles(uint32_t sbase, int stage, int tid,
                                            const __half* Ah, const __half* Al,
                                            const __half* Bh, const __half* Bl,
                                            int bm, int bn, int KPAD, int chunk) {
    uint32_t sb = sbase + stage * STAGE_STRIDE;
#pragma unroll
    for (int it = 0; it < 4; it++) {
        int i = tid + it * 256;            // 0..1023 : 128 rows x 8 16B-units
        int row = i >> 3, c16 = i & 7;
        uint32_t d = sb + row * 144 + c16 * 16;
        const __half* sa = Ah + (size_t)(bm + row) * KPAD + chunk * 64 + c16 * 8;
        CP16(d, sa);
        if (TP) {
            const __half* sl = Al + (size_t)(bm + row) * KPAD + chunk * 64 + c16 * 8;
            CP16(d + 18432, sl);
        }
    }
#pragma unroll
    for (int it = 0; it < 2; it++) {
        int i = tid + it * 256;            // 0..511 : 64 rows x 8 16B-units
        int row = i >> 3, c16 = i & 7;
        uint32_t d = sb + 36864 + row * 144 + c16 * 16;
        const __half* sbh = Bh + (size_t)(bn + row) * KPAD + chunk * 64 + c16 * 8;
        const __half* sbl = Bl + (size_t)(bn + row) * KPAD + chunk * 64 + c16 * 8;
        CP16(d, sbh);
        CP16(d + 9216, sbl);
    }
}

// ================= mma.sync fp16 GEMM, double-buffered, K-chunk 64, 1 sync/chunk =========
// TP=1: C = (Ah+Al)@(Bh+Bl)^T dropping AlBl (err ~2^-22)
// TP=0: C = Ah@(Bh+Bl)^T (err ~2^-11; A-lo never loaded)
// block 128x64, 8 warps (4m x 2n); fused column stats optional.
// Output: Cl!=null -> hi/lo fp16 pair; Cl==null -> single fp16 in Ch.
template <int NCH, int TP>
__global__ void __launch_bounds__(256, 2)
mma_gemm(const __half* __restrict__ Ah, const __half* __restrict__ Al,
         const __half* __restrict__ Bh, const __half* __restrict__ Bl,
         const float* __restrict__ biasf,
         __half* __restrict__ Ch, __half* __restrict__ Cl,
         int KPAD, int do_relu,
         float* __restrict__ gsum, float* __restrict__ gsq) {
    extern __shared__ char dsm[];
    float* scs = (float*)(dsm + 2 * STAGE_STRIDE);
    float* scq = scs + 64;
    uint32_t sbase = smem_u32(dsm);

    int tid = threadIdx.x;
    int wid = tid >> 5, lane = tid & 31;
    int bm = blockIdx.y * 128, bn = blockIdx.x * 64;
    int wm = wid & 3, wn = wid >> 2;

    if (tid < 64) { scs[tid] = 0.f; scq[tid] = 0.f; }

    float acc[2][4][4];
#pragma unroll
    for (int i = 0; i < 2; i++)
#pragma unroll
        for (int j = 0; j < 4; j++)
#pragma unroll
            for (int k = 0; k < 4; k++) acc[i][j][k] = 0.f;

    int g = lane >> 3, r = lane & 7;
    int frag_row = (g & 1) * 8 + r;
    int frag_col = (g >> 1) * 8;

    issue_tiles<TP>(sbase, 0, tid, Ah, Al, Bh, Bl, bm, bn, KPAD, 0);
    CP_COMMIT();

#pragma unroll
    for (int c = 0; c < NCH; c++) {
        // wait for stage c, publish it; the same barrier fences compute(c-1)
        // readers before issue(c+1) -- and (transitively) issue(c+2) overwriting
        // buffer (c&1) can only happen after next iteration's barrier.
        CP_WAIT0();
        __syncthreads();
        if (c + 1 < NCH) {
            issue_tiles<TP>(sbase, (c + 1) & 1, tid, Ah, Al, Bh, Bl, bm, bn, KPAD, c + 1);
            CP_COMMIT();
        }

        uint32_t baseAh = sbase + (c & 1) * STAGE_STRIDE;
        uint32_t baseAl = baseAh + 18432;
        uint32_t baseBh = baseAh + 36864;
        uint32_t baseBl = baseAh + 46080;
#pragma unroll
        for (int ks = 0; ks < 4; ks++) {
            int k0 = ks * 16;
            uint32_t ah[2][4], al[2][4], bh[2][4], bl[2][4];
#pragma unroll
            for (int mi = 0; mi < 2; mi++) {
                int row = wm * 32 + mi * 16 + frag_row;
                uint32_t off = (uint32_t)(row * AROW + k0 + frag_col) * 2;
                ldsm4(ah[mi], baseAh + off);
                if (TP) ldsm4(al[mi], baseAl + off);
            }
#pragma unroll
            for (int j = 0; j < 2; j++) {
                int row = wn * 32 + j * 16 + frag_row;
                uint32_t off = (uint32_t)(row * AROW + k0 + frag_col) * 2;
                ldsm4(bh[j], baseBh + off);
                ldsm4(bl[j], baseBl + off);
            }
#pragma unroll
            for (int mi = 0; mi < 2; mi++)
#pragma unroll
                for (int nt = 0; nt < 4; nt++) {
                    int j = nt >> 1, sel = nt & 1;
                    mma16816f(acc[mi][nt], ah[mi], bh[j][sel], bh[j][sel + 2]);
                    mma16816f(acc[mi][nt], ah[mi], bl[j][sel], bl[j][sel + 2]);
                    if (TP)
                        mma16816f(acc[mi][nt], al[mi], bh[j][sel], bh[j][sel + 2]);
                }
        }
    }

    // ---- epilogue ----
    int tm = lane >> 2;
    int tn = (lane & 3) * 2;
    bool dosum = (gsum != nullptr);
#pragma unroll
    for (int nt = 0; nt < 4; nt++) {
        float s0 = 0.f, s1 = 0.f, q0 = 0.f, q1 = 0.f;
        int col = bn + wn * 32 + nt * 8 + tn;
        float b0 = biasf[col], b1 = biasf[col + 1];
#pragma unroll
        for (int mi = 0; mi < 2; mi++) {
            int row0 = bm + wm * 32 + mi * 16 + tm;
            float v0 = acc[mi][nt][0] + b0, v1 = acc[mi][nt][1] + b1;
            float v2 = acc[mi][nt][2] + b0, v3 = acc[mi][nt][3] + b1;
            if (do_relu) {
                v0 = fmaxf(v0, 0.f); v1 = fmaxf(v1, 0.f);
                v2 = fmaxf(v2, 0.f); v3 = fmaxf(v3, 0.f);
            }
            __half h0 = __float2half_rn(v0), h1 = __float2half_rn(v1);
            __half h2 = __float2half_rn(v2), h3 = __float2half_rn(v3);
            uint32_t ph01 = ((uint32_t)__half_as_ushort(h1) << 16) | __half_as_ushort(h0);
            uint32_t ph23 = ((uint32_t)__half_as_ushort(h3) << 16) | __half_as_ushort(h2);
            *(uint32_t*)&Ch[(size_t)row0 * D + col] = ph01;
            *(uint32_t*)&Ch[(size_t)(row0 + 8) * D + col] = ph23;
            if (Cl) {
                __half l0 = __float2half_rn(v0 - __half2float(h0));
                __half l1 = __float2half_rn(v1 - __half2float(h1));
                __half l2 = __float2half_rn(v2 - __half2float(h2));
                __half l3 = __float2half_rn(v3 - __half2float(h3));
                uint32_t pl01 = ((uint32_t)__half_as_ushort(l1) << 16) | __half_as_ushort(l0);
                uint32_t pl23 = ((uint32_t)__half_as_ushort(l3) << 16) | __half_as_ushort(l2);
                *(uint32_t*)&Cl[(size_t)row0 * D + col] = pl01;
                *(uint32_t*)&Cl[(size_t)(row0 + 8) * D + col] = pl23;
            }
            s0 += v0 + v2; s1 += v1 + v3;
            q0 += v0 * v0 + v2 * v2; q1 += v1 * v1 + v3 * v3;
        }
        if (dosum) {
#pragma unroll
            for (int o = 4; o < 32; o <<= 1) {
                s0 += __shfl_xor_sync(0xffffffffu, s0, o);
                s1 += __shfl_xor_sync(0xffffffffu, s1, o);
                q0 += __shfl_xor_sync(0xffffffffu, q0, o);
                q1 += __shfl_xor_sync(0xffffffffu, q1, o);
            }
            if (lane < 4) {
                int cl = wn * 32 + nt * 8 + lane * 2;
                atomicAdd(&scs[cl], s0); atomicAdd(&scs[cl + 1], s1);
                atomicAdd(&scq[cl], q0); atomicAdd(&scq[cl + 1], q1);
            }
        }
    }
    if (dosum) {
        __syncthreads();
        if (tid < 64) {
            atomicAdd(&gsum[bn + tid], scs[tid]);
            atomicAdd(&gsq[bn + tid], scq[tid]);
        }
    }
}

// ================= graph kernels =================
__global__ void deg_kernel(const int* __restrict__ dst) {
    int e = blockIdx.x * blockDim.x + threadIdx.x;
    if (e < NEDGES) atomicAdd(&g_degi[dst[e]], 1);
}
__global__ void isq_kernel() {
    int n = blockIdx.x * blockDim.x + threadIdx.x;
    if (n < NNODES) g_isq[n] = rsqrtf((float)g_degi[n] + 1.0f);
}
__global__ void scan_kernel() {
    __shared__ int sh[1024];
    int tid = threadIdx.x;
    int base = tid * 32;
    int local[32];
    int s = 0;
    for (int i = 0; i < 32; i++) { local[i] = s; s += g_degi[base + i]; }
    sh[tid] = s;
    __syncthreads();
    for (int off = 1; off < 1024; off <<= 1) {
        int v = 0;
        if (tid >= off) v = sh[tid - off];
        __syncthreads();
        if (tid >= off) sh[tid] += v;
        __syncthreads();
    }
    int prev = (tid == 0) ? 0 : sh[tid - 1];
    for (int i = 0; i < 32; i++) {
        g_off[base + i] = prev + local[i];
        g_cursor[base + i] = prev + local[i];
    }
    if (tid == 1023) g_off[NNODES] = sh[1023];
}
__global__ void scatter_kernel(const int* __restrict__ src, const int* __restrict__ dst) {
    int e = blockIdx.x * blockDim.x + threadIdx.x;
    if (e < NEDGES) {
        int d = dst[e];
        int p = atomicAdd(&g_cursor[d], 1);
        g_csr[p] = src[e];
    }
}

// GCN aggregation: fp16 in (u32/half2 loads), fp32 accumulate, bias+relu, single fp16 out
#define AGG_T 192
__global__ void __launch_bounds__(AGG_T)
agg_kernel(const __half* __restrict__ xw, const float* __restrict__ bias,
           __half* __restrict__ oh) {
    int n = blockIdx.x;
    int t = threadIdx.x;
    float isqn = g_isq[n];
    float sc = isqn * isqn;
    const uint32_t* selfrow = (const uint32_t*)(xw + (size_t)n * D);
    uint32_t su = selfrow[t];
    __half2 sh2 = *(__half2*)&su;
    float a0 = __low2float(sh2) * sc;
    float a1 = __high2float(sh2) * sc;

    int beg = g_off[n], end = g_off[n + 1];
    __shared__ int ssrc[AGG_T];
    __shared__ float scoef[AGG_T];
    for (int p = beg; p < end; p += AGG_T) {
        int cnt = min(AGG_T, end - p);
        __syncthreads();
        if (t < cnt) {
            int s = g_csr[p + t];
            ssrc[t] = s;
            scoef[t] = g_isq[s] * isqn;
        }
        __syncthreads();
        for (int j = 0; j < cnt; j++) {
            int s = ssrc[j];
            float c = scoef[j];
            uint32_t u = ((const uint32_t*)(xw + (size_t)s * D))[t];
            __half2 h2v = *(__half2*)&u;
            a0 += __low2float(h2v) * c;
            a1 += __high2float(h2v) * c;
        }
    }
    float2 bb = *(const float2*)(bias + 2 * t);
    float v0 = fmaxf(a0 + bb.x, 0.f);
    float v1 = fmaxf(a1 + bb.y, 0.f);
    __half h0 = __float2half_rn(v0);
    __half h1 = __float2half_rn(v1);
    uint32_t ph = ((uint32_t)__half_as_ushort(h1) << 16) | __half_as_ushort(h0);
    ((uint32_t*)(oh + (size_t)n * D))[t] = ph;
}

// ================= tail kernels =================
__global__ void sel_kernel(const int* __restrict__ mask) {
    int b = threadIdx.x;
    int c = 0;
    for (int i = 0; i < NGRAPH; i++) {
        if (mask[b * NGRAPH + i]) {
            if (c < 2) g_sel[b * 2 + c] = i;
            c++;
        }
    }
}
// fused: gather 2 masked nodes (BN slot-4 affine inline) -> relu(flat @ w_cat + b_cat)
// + fused column stats (slot 5). One block per sample, 768 threads.
__global__ void cat_gemm_kernel(const __half* __restrict__ H,
                                const float* __restrict__ sum4, const float* __restrict__ sq4,
                                const float* __restrict__ gam, const float* __restrict__ bet,
                                const float* __restrict__ Wc, const float* __restrict__ bc,
                                float* __restrict__ sum, float* __restrict__ sq) {
    __shared__ float sh[EFEAT];
    int b = blockIdx.x, t = threadIdx.x;
    {
        int j = t / D, tloc = t % D;
        int node = b * NGRAPH + g_sel[b * 2 + j];
        float v = __half2float(H[(size_t)node * D + tloc]);
        float s = bn_scale_of(sum4, sq4, tloc, (float)NNODES, gam);
        float shf = bn_shift_of(sum4, sq4, tloc, (float)NNODES, gam, bet);
        sh[t] = v * s + shf;
    }
    __syncthreads();
    float s = bc[t];
    for (int k = 0; k < EFEAT; k++) s += sh[k] * Wc[(size_t)k * EFEAT + t];
    s = fmaxf(s, 0.f);
    g_outc[b * EFEAT + t] = s;
    atomicAdd(&sum[t], s);
    atomicAdd(&sq[t], s * s);
}
__global__ void attout_kernel(const float* __restrict__ sum5, const float* __restrict__ sq5,
                              const float* __restrict__ sum6, const float* __restrict__ sq6,
                              const float* __restrict__ bg, const float* __restrict__ bb,
                              const float* __restrict__ wout, const float* __restrict__ bout,
                              float* __restrict__ out) {
    __shared__ float satt[EFEAT];
    int b = blockIdx.x, t = threadIdx.x;
    float Bf = (float)BATCH;
    float m0 = sum5[t] / Bf, v0 = sq5[t] / Bf - m0 * m0;
    float oc = bg[t] * (g_outc[b * EFEAT + t] - m0) * rsqrtf(v0 + EPS) + bb[t];
    float m1 = sum6[t] / Bf, v1 = sq6[t] / Bf - m1 * m1;
    float hh = bg[EFEAT + t] * (g_hsent[b * EFEAT + t] - m1) * rsqrtf(v1 + EPS) + bb[EFEAT + t];
    satt[t] = hh + oc;
    __syncthreads();
    int w = t >> 5, lane = t & 31;
    if (w < 3) {
        int c = w;
        float p = 0.f;
        for (int e = lane; e < EFEAT; e += 32) p += satt[e] * wout[e * 3 + c];
#pragma unroll
        for (int o = 16; o > 0; o >>= 1) p += __shfl_xor_sync(0xffffffffu, p, o);
        if (lane == 0) out[b * 3 + c] = p + bout[c];
    }
}

// ============================== launch ==============================
extern "C" void kernel_launch(void* const* d_in, const int* in_sizes, int n_in,
                              void* d_out, int out_size) {
    const float* last_h  = (const float*)d_in[0];
    const float* first_h = (const float*)d_in[1];
    const float* x_nodes = (const float*)d_in[2];
    const int*   eidx    = (const int*)d_in[3];
    const int*   mask    = (const int*)d_in[4];
    const float* w_pre1  = (const float*)d_in[5];
    const float* b_pre1  = (const float*)d_in[6];
    const float* w_pre2  = (const float*)d_in[7];
    const float* b_pre2  = (const float*)d_in[8];
    const float* w_conv  = (const float*)d_in[9];
    const float* b_conv  = (const float*)d_in[10];
    const float* bng_g   = (const float*)d_in[11];
    const float* bng_b   = (const float*)d_in[12];
    const float* w_post1 = (const float*)d_in[13];
    const float* b_post1 = (const float*)d_in[14];
    const float* w_post2 = (const float*)d_in[15];
    const float* b_post2 = (const float*)d_in[16];
    const float* w_cat   = (const float*)d_in[17];
    const float* b_cat   = (const float*)d_in[18];
    const float* bn_g    = (const float*)d_in[19];
    const float* bn_b    = (const float*)d_in[20];
    const float* w_out   = (const float*)d_in[21];
    const float* b_out   = (const float*)d_in[22];
    float* out = (float*)d_out;

    const int* esrc = eidx;
    const int* edst = eidx + NEDGES;

    float *sum, *sq, *hs, *bfp;
    __half *x0h, *x0l, *h1, *l1, *h2, *wth, *wtl, *xw;
    cudaGetSymbolAddress((void**)&sum, g_sum);
    cudaGetSymbolAddress((void**)&sq, g_sq);
    cudaGetSymbolAddress((void**)&hs, g_hsent);
    cudaGetSymbolAddress((void**)&bfp, g_biasf);
    cudaGetSymbolAddress((void**)&xw, g_xw);
    cudaGetSymbolAddress((void**)&x0h, g_x0h);
    cudaGetSymbolAddress((void**)&x0l, g_x0l);
    cudaGetSymbolAddress((void**)&h1, g_h1);
    cudaGetSymbolAddress((void**)&l1, g_l1);
    cudaGetSymbolAddress((void**)&h2, g_h2);
    cudaGetSymbolAddress((void**)&wth, g_wth);
    cudaGetSymbolAddress((void**)&wtl, g_wtl);

    cudaFuncSetAttribute(mma_gemm<5, 1>, cudaFuncAttributeMaxDynamicSharedMemorySize, DYN_SMEM);
    cudaFuncSetAttribute(mma_gemm<6, 1>, cudaFuncAttributeMaxDynamicSharedMemorySize, DYN_SMEM);
    cudaFuncSetAttribute(mma_gemm<6, 0>, cudaFuncAttributeMaxDynamicSharedMemorySize, DYN_SMEM);

    const float Mf = (float)NNODES;
    dim3 gg(D / 64, NNODES / 128);   // (6, 256) — 128x64 tiles, 2 CTA/SM

    cudaStream_t s1, s2;
    cudaEvent_t e0, e1, e2, e3;
    cudaStreamCreateWithFlags(&s1, cudaStreamNonBlocking);
    cudaStreamCreateWithFlags(&s2, cudaStreamNonBlocking);
    cudaEventCreateWithFlags(&e0, cudaEventDisableTiming);
    cudaEventCreateWithFlags(&e1, cudaEventDisableTiming);
    cudaEventCreateWithFlags(&e2, cudaEventDisableTiming);
    cudaEventCreateWithFlags(&e3, cudaEventDisableTiming);

    zero_kernel<<<192, 256>>>();
    cudaEventRecord(e0, 0);
    cudaStreamWaitEvent(s1, e0, 0);
    cudaStreamWaitEvent(s2, e0, 0);

    // side stream 1: sentence branch + its stats (slot 6)
    hsent_kernel<<<dim3(BATCH, 4), EFEAT, 0, s1>>>(last_h, first_h);
    stats_kernel<<<1, EFEAT, 0, s1>>>(hs, BATCH, EFEAT, sum + 6 * EFEAT, sq + 6 * EFEAT);
    cudaEventRecord(e1, s1);

    // side stream 2: stage-0 weight prep (joins before GEMM1), then CSR chain
    wprep0_kernel<<<(D * 320 + 255) / 256, 256, 0, s2>>>(w_pre1, 300, 320,
                                                         wth + 0 * D * D, wtl + 0 * D * D);
    cudaEventRecord(e3, s2);
    deg_kernel<<<NEDGES / 256, 256, 0, s2>>>(edst);
    isq_kernel<<<NNODES / 256, 256, 0, s2>>>();
    scan_kernel<<<1, 1024, 0, s2>>>();
    scatter_kernel<<<NEDGES / 256, 256, 0, s2>>>(esrc, edst);
    sel_kernel<<<1, BATCH, 0, s2>>>(mask);
    cudaEventRecord(e2, s2);

    // main: input prep
    xprep_kernel<<<(NNODES * 320 + 255) / 256, 256>>>(x_nodes);
    cudaStreamWaitEvent(0, e3, 0);

    // GEMM1 (3-pass, K=320: 5 chunks) -> h1/l1, fused stats slot 0 (bng row 0)
    mma_gemm<5, 1><<<gg, 256, DYN_SMEM>>>(x0h, x0l, wth + 0 * D * D, wtl + 0 * D * D, b_pre1,
                                          h1, l1, 320, 1, sum + 0 * EFEAT, sq + 0 * EFEAT);
    fold_kernel<<<D, 128>>>(w_pre2, sum + 0 * EFEAT, sq + 0 * EFEAT,
                            bng_g + 0 * D, bng_b + 0 * D, Mf, b_pre2,
                            wth + 1 * D * D, wtl + 1 * D * D, bfp + 1 * D);

    // GEMM2 (3-pass, single fp16 out — G3 consumes hi only) -> h2, stats slot 1 (bng row 1)
    mma_gemm<6, 1><<<gg, 256, DYN_SMEM>>>(h1, l1, wth + 1 * D * D, wtl + 1 * D * D, bfp + 1 * D,
                                          h2, nullptr, D, 1, sum + 1 * EFEAT, sq + 1 * EFEAT);
    fold_kernel<<<D, 128>>>(w_conv + 2 * D * D, sum + 1 * EFEAT, sq + 1 * EFEAT,
                            bng_g + 1 * D, bng_b + 1 * D, Mf, nullptr,
                            wth + 2 * D * D, wtl + 2 * D * D, bfp + 2 * D);

    // GEMM3 (2-pass; output fp16-rounded anyway) -> single fp16 xw
    mma_gemm<6, 0><<<gg, 256, DYN_SMEM>>>(h2, nullptr, wth + 2 * D * D, wtl + 2 * D * D, bfp + 2 * D,
                                          xw, nullptr, D, 0, nullptr, nullptr);

    // join CSR stream, aggregate (single fp16 out), stats slot 2 (bng row 4)
    cudaStreamWaitEvent(0, e2, 0);
    agg_kernel<<<NNODES, AGG_T>>>(xw, b_conv + 2 * D, h1);
    stats_f16_kernel<<<256, D>>>(h1, sum + 2 * EFEAT, sq + 2 * EFEAT);
    fold_kernel<<<D, 128>>>(w_post1, sum + 2 * EFEAT, sq + 2 * EFEAT,
                            bng_g + 4 * D, bng_b + 4 * D, Mf, b_post1,
                            wth + 3 * D * D, wtl + 3 * D * D, bfp + 3 * D);

    // GEMM4 (2-pass, single fp16 out) -> h2, stats slot 3 (bng row 5)
    mma_gemm<6, 0><<<gg, 256, DYN_SMEM>>>(h1, nullptr, wth + 3 * D * D, wtl + 3 * D * D, bfp + 3 * D,
                                          h2, nullptr, D, 1, sum + 3 * EFEAT, sq + 3 * EFEAT);
    fold_kernel<<<D, 128>>>(w_post2, sum + 3 * EFEAT, sq + 3 * EFEAT,
                            bng_g + 5 * D, bng_b + 5 * D, Mf, b_post2,
                            wth + 4 * D * D, wtl + 4 * D * D, bfp + 4 * D);

    // GEMM5 (2-pass, single fp16 out; only 128 rows + stats consumed) -> h1, stats slot 4
    mma_gemm<6, 0><<<gg, 256, DYN_SMEM>>>(h2, nullptr, wth + 4 * D * D, wtl + 4 * D * D, bfp + 4 * D,
                                          h1, nullptr, D, 1, sum + 4 * EFEAT, sq + 4 * EFEAT);

    // tail: fused gather+cat-MLP (+stats slot 5) -> att+out
    cat_gemm_kernel<<<BATCH, EFEAT>>>(h1, sum + 4 * EFEAT, sq + 4 * EFEAT,
                                      bng_g + 6 * D, bng_b + 6 * D,
                                      w_cat, b_cat, sum + 5 * EFEAT, sq + 5 * EFEAT);
    cudaStreamWaitEvent(0, e1, 0);
    attout_kernel<<<BATCH, EFEAT>>>(sum + 5 * EFEAT, sq + 5 * EFEAT,
                                    sum + 6 * EFEAT, sq + 6 * EFEAT,
                                    bn_g, bn_b, w_out, b_out, out);

    cudaEventDestroy(e0);
    cudaEventDestroy(e1);
    cudaEventDestroy(e2);
    cudaEventDestroy(e3);
    cudaStreamDestroy(s1);
    cudaStreamDestroy(s2);
}